// round 15
// baseline (speedup 1.0000x reference)
#include <cuda_runtime.h>
#include <math.h>

#define BB 16
#define NN 2048
#define CC 64
#define EE 16
#define OO 64
// K=2, C=64 -> KC = 128

typedef unsigned long long ULL;

// ---------------- f32x2 packed-FMA helpers (sm_100+) -------------------------
__device__ __forceinline__ ULL pack2(float a, float b) {
    ULL r;
    asm("mov.b64 %0, {%1, %2};" : "=l"(r) : "f"(a), "f"(b));
    return r;
}
__device__ __forceinline__ void fma2(ULL& d, ULL a, ULL b) {
    asm("fma.rn.f32x2 %0, %1, %2, %0;" : "+l"(d) : "l"(a), "l"(b));
}
__device__ __forceinline__ float2 unpack2(ULL v) {
    float x, y;
    asm("mov.b64 {%0, %1}, %2;" : "=f"(x), "=f"(y) : "l"(v));
    return make_float2(x, y);
}

// ---------------- scratch (device globals; no allocations allowed) ----------
__device__ float g_nodevec[BB * NN * EE];                    // 2 MB
__device__ float g_dsum[8 * BB * NN];                        // 1 MB (8 m-split partials)
__device__ float g_dinv[BB * NN];                            // 128 KB (reduced rsqrt)
__device__ float g_W[(size_t)NN * 128 * 64];                 // 64 MB (n, kc, o)
__device__ float g_xg2p[(size_t)8 * BB * NN * CC];           // 64 MB (8 m-split partials)

// ---------------- K1: hyper-MLP -> nodevec ---------------------------------
__global__ void k_nodevec(const float* __restrict__ x, const float* __restrict__ emb0,
                          const float* __restrict__ w1, const float* __restrict__ b1,
                          const float* __restrict__ w2, const float* __restrict__ b2,
                          const float* __restrict__ w3, const float* __restrict__ b3)
{
    __shared__ float s_w1[1024];
    __shared__ float s_b1[16], s_w2[32], s_b2[2], s_w3[32], s_b3[16];
    int tid = threadIdx.x;
    for (int i = tid; i < 1024; i += 256) s_w1[i] = w1[i];
    if (tid < 16) s_b1[tid] = b1[tid];
    if (tid < 32) s_w2[tid] = w2[tid];
    if (tid < 2)  s_b2[tid] = b2[tid];
    if (tid >= 32 && tid < 64) s_w3[tid - 32] = w3[tid - 32];
    if (tid >= 64 && tid < 80) s_b3[tid - 64] = b3[tid - 64];
    __syncthreads();

    int row = blockIdx.x * 256 + tid;
    const float4* xr = (const float4*)(x + (size_t)row * 64);
    float xv[64];
#pragma unroll
    for (int i = 0; i < 16; i++) {
        float4 t = xr[i];
        xv[4*i] = t.x; xv[4*i+1] = t.y; xv[4*i+2] = t.z; xv[4*i+3] = t.w;
    }
    float h[16];
#pragma unroll
    for (int j = 0; j < 16; j++) h[j] = s_b1[j];
#pragma unroll
    for (int c = 0; c < 64; c++) {
        float xc = xv[c];
#pragma unroll
        for (int j = 0; j < 16; j++) h[j] = fmaf(xc, s_w1[c * 16 + j], h[j]);
    }
#pragma unroll
    for (int j = 0; j < 16; j++) h[j] = 1.0f / (1.0f + expf(-h[j]));

    float h2[2];
#pragma unroll
    for (int m = 0; m < 2; m++) {
        float a = s_b2[m];
#pragma unroll
        for (int j = 0; j < 16; j++) a = fmaf(h[j], s_w2[j * 2 + m], a);
        h2[m] = 1.0f / (1.0f + expf(-a));
    }

    float filt[16];
#pragma unroll
    for (int e = 0; e < 16; e++)
        filt[e] = s_b3[e] + h2[0] * s_w3[e] + h2[1] * s_w3[16 + e];

    const float4* e0p = (const float4*)(emb0 + (size_t)row * 16);
    float4* nvout = (float4*)(g_nodevec + (size_t)row * 16);
#pragma unroll
    for (int q = 0; q < 4; q++) {
        float4 ev = e0p[q];
        float4 r;
        r.x = tanhf(ev.x * filt[4*q + 0]);
        r.y = tanhf(ev.y * filt[4*q + 1]);
        r.z = tanhf(ev.z * filt[4*q + 2]);
        r.w = tanhf(ev.w * filt[4*q + 3]);
        nvout[q] = r;
    }
}

// ---------------- K2: W[n,kc,o] = sum_e emb1[n,e] * wp[e,kc,o] (f32x2) -------
__global__ void k_wpre(const float* __restrict__ emb1, const float* __restrict__ wp)
{
    __shared__ float s_emb[256];
    int tid = threadIdx.x;
    int n0 = blockIdx.y * 16;
    s_emb[tid] = emb1[(size_t)n0 * 16 + tid];
    __syncthreads();

    int r4 = blockIdx.x * 256 + tid;
    const float4* wp4 = (const float4*)wp;
    ulonglong2 wv[16];
#pragma unroll
    for (int e = 0; e < 16; e++) {
        float4 t = wp4[(size_t)e * 2048 + r4];
        wv[e].x = pack2(t.x, t.y);
        wv[e].y = pack2(t.z, t.w);
    }

#pragma unroll 4
    for (int nn = 0; nn < 16; nn++) {
        ULL a0 = 0ULL, a1 = 0ULL;
#pragma unroll
        for (int e = 0; e < 16; e++) {
            float s = s_emb[nn * 16 + e];
            ULL sp = pack2(s, s);
            fma2(a0, sp, wv[e].x);
            fma2(a1, sp, wv[e].y);
        }
        float2 r0 = unpack2(a0), r1 = unpack2(a1);
        ((float4*)g_W)[(size_t)(n0 + nn) * 2048 + r4] =
            make_float4(r0.x, r0.y, r1.x, r1.y);
    }
}

// ---------------- K3: partial dsum[ms,b,n], 2 n-rows per thread -------------
// grid (8, 16, 8), 128 threads. Rows n0+tid, n0+128+tid; 256 m per block.
__global__ void __launch_bounds__(128) k_dinv()
{
    __shared__ float s_vmT[16][128];
    int tid = threadIdx.x;
    int b = blockIdx.y;
    int ms = blockIdx.z;
    int n0 = blockIdx.x * 256;
    const float* nvb = g_nodevec + (size_t)b * NN * 16;

    ULL vnd[2][16];
#pragma unroll
    for (int r = 0; r < 2; r++) {
        const float4* p = (const float4*)(nvb + (size_t)(n0 + r * 128 + tid) * 16);
#pragma unroll
        for (int q = 0; q < 4; q++) {
            float4 t = p[q];
            vnd[r][4*q+0] = pack2(t.x, t.x);
            vnd[r][4*q+1] = pack2(t.y, t.y);
            vnd[r][4*q+2] = pack2(t.z, t.z);
            vnd[r][4*q+3] = pack2(t.w, t.w);
        }
    }
    float sacc0 = 0.f, sacc1 = 0.f;
    for (int mt = 0; mt < 2; mt++) {
        int m0 = ms * 256 + mt * 128;
        __syncthreads();
        {
            const float4* q = (const float4*)(nvb + (size_t)(m0 + tid) * 16);
#pragma unroll
            for (int i = 0; i < 4; i++) {
                float4 t = q[i];
                s_vmT[4*i+0][tid] = t.x; s_vmT[4*i+1][tid] = t.y;
                s_vmT[4*i+2][tid] = t.z; s_vmT[4*i+3][tid] = t.w;
            }
        }
        __syncthreads();
#pragma unroll 2
        for (int mm = 0; mm < 128; mm += 4) {
            ULL d00 = 0ULL, d01 = 0ULL, d10 = 0ULL, d11 = 0ULL;
#pragma unroll
            for (int e = 0; e < 16; e++) {
                ulonglong2 v = *(const ulonglong2*)&s_vmT[e][mm];
                fma2(d00, vnd[0][e], v.x); fma2(d01, vnd[0][e], v.y);
                fma2(d10, vnd[1][e], v.x); fma2(d11, vnd[1][e], v.y);
            }
            float2 a0 = unpack2(d00), a1 = unpack2(d01);
            float2 b0 = unpack2(d10), b1 = unpack2(d11);
            sacc0 += (fmaxf(a0.x, 0.f) + fmaxf(a0.y, 0.f)) +
                     (fmaxf(a1.x, 0.f) + fmaxf(a1.y, 0.f));
            sacc1 += (fmaxf(b0.x, 0.f) + fmaxf(b0.y, 0.f)) +
                     (fmaxf(b1.x, 0.f) + fmaxf(b1.y, 0.f));
        }
    }
    size_t base = ((size_t)ms * BB + b) * NN + n0 + tid;
    g_dsum[base] = sacc0;
    g_dsum[base + 128] = sacc1;
}

// ---------------- K3b: reduce dsum partials -> g_dinv = rsqrt(sum) ----------
__global__ void k_dred()
{
    int i = blockIdx.x * 256 + threadIdx.x;     // 0 .. BB*NN-1
    float s = 0.f;
#pragma unroll
    for (int p = 0; p < 8; p++) s += g_dsum[(size_t)p * BB * NN + i];
    g_dinv[i] = rsqrtf(s);
}

// ---------------- K4: x_g2 partials: L @ x (R6 best config) ------------------
// 128 threads; grid (16 nt, 16 b, 8 ms). m-chunk = 64; 4 mi per block.
// smem 60KB, <=170 regs -> 3 CTAs/SM. Thread tile: 8 rows x 8 cols.
// sA swizzle: A[row][col] at sA[row*64 + (((col>>2) ^ ((row>>2)&3))<<2) + (col&3)].
__global__ void __launch_bounds__(128, 3) k_xg2(const float* __restrict__ x)
{
    extern __shared__ float sm[];
    float* sA   = sm;                    // 128*64 swizzled (32KB)
    float* sXm  = sA + 128 * 64;         // 64*64 (16KB)
    float* sVnT = sXm + 64 * 64;         // 16*128 [e][n] (8KB)
    float* sVmT = sVnT + 16 * 128;       // 16*64 [e][m] (4KB)

    int tid = threadIdx.x;
    int nt = blockIdx.x, b = blockIdx.y, ms = blockIdx.z;
    int n0 = nt * 128;
    const float* nvb = g_nodevec + (size_t)b * NN * 16;
    const float* dvb = g_dinv + (size_t)b * NN;

    int rgrp = tid >> 3;                 // 0..15 -> rows rgrp*8 .. +8
    int cgrp = tid & 7;
    int row0 = rgrp * 8;
    int key0 = (rgrp * 2) & 3;           // (row>>2)&3 for rows row0..row0+3
    int key1 = (rgrp * 2 + 1) & 3;       // for rows row0+4..row0+7
    int c0 = cgrp * 4, c1 = 32 + cgrp * 4;

    // load VnT (d-scaled), once: 1 row per thread
    {
        int r = tid;
        float dv = dvb[n0 + r];
        const float4* p = (const float4*)(nvb + (size_t)(n0 + r) * 16);
#pragma unroll
        for (int q = 0; q < 4; q++) {
            float4 t = p[q];
            sVnT[(q*4+0)*128 + r] = t.x*dv; sVnT[(q*4+1)*128 + r] = t.y*dv;
            sVnT[(q*4+2)*128 + r] = t.z*dv; sVnT[(q*4+3)*128 + r] = t.w*dv;
        }
    }

    ULL acc[8][4];
#pragma unroll
    for (int i = 0; i < 8; i++)
#pragma unroll
        for (int j = 0; j < 4; j++) acc[i][j] = 0ULL;

    for (int mi = 0; mi < 4; mi++) {
        int m0 = ms * 256 + mi * 64;
        __syncthreads();
        // stage VmT (d-scaled): 64 rows, 2 threads/row
        {
            int r = tid >> 1, half = tid & 1;
            float dv = dvb[m0 + r];
            const float4* p = (const float4*)(nvb + (size_t)(m0 + r) * 16 + half * 8);
            float4 t0 = p[0], t1 = p[1];
            int e0 = half * 8;
            sVmT[(e0+0)*64 + r] = t0.x*dv; sVmT[(e0+1)*64 + r] = t0.y*dv;
            sVmT[(e0+2)*64 + r] = t0.z*dv; sVmT[(e0+3)*64 + r] = t0.w*dv;
            sVmT[(e0+4)*64 + r] = t1.x*dv; sVmT[(e0+5)*64 + r] = t1.y*dv;
            sVmT[(e0+6)*64 + r] = t1.z*dv; sVmT[(e0+7)*64 + r] = t1.w*dv;
        }
        // stage X chunk: 64x64 = 1024 float4, 8 per thread
        {
            const float4* xp = (const float4*)(x + ((size_t)b * NN + m0) * 64);
            float4* xs = (float4*)sXm;
#pragma unroll
            for (int i = 0; i < 8; i++) xs[tid + i * 128] = xp[tid + i * 128];
        }
        __syncthreads();

        // ---- Phase A: A = relu((d.Vn)(d.Vm)^T) -> swizzled sA (4-row passes)
#pragma unroll
        for (int pass = 0; pass < 2; pass++) {
            int prow = row0 + pass * 4;
            int key = pass ? key1 : key0;
            int l0p = (cgrp ^ key) << 2;
            int l1p = ((8 + cgrp) ^ key) << 2;
            ULL pa[4][4];
#pragma unroll
            for (int i = 0; i < 4; i++)
#pragma unroll
                for (int j = 0; j < 4; j++) pa[i][j] = 0ULL;
#pragma unroll
            for (int e = 0; e < 16; e++) {
                float4 vn = *(const float4*)&sVnT[e * 128 + prow];
                ulonglong2 va = *(const ulonglong2*)&sVmT[e * 64 + c0];
                ulonglong2 vb = *(const ulonglong2*)&sVmT[e * 64 + c1];
                float vv[4] = {vn.x, vn.y, vn.z, vn.w};
#pragma unroll
                for (int i = 0; i < 4; i++) {
                    ULL ad = pack2(vv[i], vv[i]);
                    fma2(pa[i][0], ad, va.x); fma2(pa[i][1], ad, va.y);
                    fma2(pa[i][2], ad, vb.x); fma2(pa[i][3], ad, vb.y);
                }
            }
#pragma unroll
            for (int i = 0; i < 4; i++) {
                int row = prow + i;
                float2 p0 = unpack2(pa[i][0]);
                float2 p1 = unpack2(pa[i][1]);
                float2 p2 = unpack2(pa[i][2]);
                float2 p3 = unpack2(pa[i][3]);
                float4 o0 = make_float4(fmaxf(p0.x, 0.f), fmaxf(p0.y, 0.f),
                                        fmaxf(p1.x, 0.f), fmaxf(p1.y, 0.f));
                float4 o1 = make_float4(fmaxf(p2.x, 0.f), fmaxf(p2.y, 0.f),
                                        fmaxf(p3.x, 0.f), fmaxf(p3.y, 0.f));
                *(float4*)&sA[row * 64 + l0p] = o0;
                *(float4*)&sA[row * 64 + l1p] = o1;
            }
        }
        __syncthreads();

        // ---- Phase B: acc += A @ Xm (8 rows x 8 cols per thread) -----------
#pragma unroll 2
        for (int kf4 = 0; kf4 < 16; kf4++) {
            int laneA = ((kf4 ^ key0) << 2);
            int laneB = ((kf4 ^ key1) << 2);
            float4 a[8];
#pragma unroll
            for (int i = 0; i < 4; i++)
                a[i] = *(const float4*)&sA[(row0 + i) * 64 + laneA];
#pragma unroll
            for (int i = 4; i < 8; i++)
                a[i] = *(const float4*)&sA[(row0 + i) * 64 + laneB];
#pragma unroll
            for (int kk = 0; kk < 4; kk++) {
                int k = kf4 * 4 + kk;
                ulonglong2 xa = *(const ulonglong2*)&sXm[k * 64 + c0];
                ulonglong2 xb = *(const ulonglong2*)&sXm[k * 64 + c1];
#pragma unroll
                for (int i = 0; i < 8; i++) {
                    float av = (kk == 0) ? a[i].x : (kk == 1) ? a[i].y
                             : (kk == 2) ? a[i].z : a[i].w;
                    ULL ad = pack2(av, av);
                    fma2(acc[i][0], ad, xa.x);
                    fma2(acc[i][1], ad, xa.y);
                    fma2(acc[i][2], ad, xb.x);
                    fma2(acc[i][3], ad, xb.y);
                }
            }
        }
    }

    // epilogue: store partial (d_n already folded in)
    float* op = g_xg2p + (((size_t)ms * BB + b) * NN + n0) * 64;
#pragma unroll
    for (int i = 0; i < 8; i++) {
        int row = row0 + i;
        float2 q0 = unpack2(acc[i][0]);
        float2 q1 = unpack2(acc[i][1]);
        float2 q2 = unpack2(acc[i][2]);
        float2 q3 = unpack2(acc[i][3]);
        *(float4*)&op[(size_t)row * 64 + c0] = make_float4(q0.x, q0.y, q1.x, q1.y);
        *(float4*)&op[(size_t)row * 64 + c1] = make_float4(q2.x, q2.y, q3.x, q3.y);
    }
}

// ---------------- K5: out = x_g @ W[n] + bias --------------------------------
// 128 threads = 16 bb x 8 og; each thread computes 8 outputs (4 ULL accs).
// Per kc: 1 LDS broadcast + 1 pack + 4 fma2.
__global__ void __launch_bounds__(128) k_out(const float* __restrict__ x,
                                             const float* __restrict__ emb1,
                                             const float* __restrict__ bias_pool,
                                             float* __restrict__ out)
{
    __shared__ float sW[128 * 64];
    __shared__ float sxg[16][128];
    __shared__ float sbp[16 * 64];
    __shared__ float semb[16];
    int n = blockIdx.x;
    int tid = threadIdx.x;
    {
        const float4* wp = (const float4*)(g_W + (size_t)n * 8192);
        float4* sW4 = (float4*)sW;
#pragma unroll
        for (int i = 0; i < 16; i++) sW4[tid + i * 128] = wp[tid + i * 128];
    }
#pragma unroll
    for (int i = 0; i < 2; i++)
        ((float4*)sbp)[tid + i * 128] = ((const float4*)bias_pool)[tid + i * 128];
    if (tid < 16) semb[tid] = emb1[(size_t)n * 16 + tid];
    {
        int bb = tid >> 3, lane = tid & 7;
        size_t rowoff = ((size_t)bb * NN + n) * 64;
        if (lane < 4) {
            const float4* xp = (const float4*)(x + rowoff);
#pragma unroll
            for (int i = 0; i < 4; i++)
                *(float4*)&sxg[bb][(lane * 4 + i) * 4] = xp[lane * 4 + i];
        } else {
            int l2 = lane - 4;
#pragma unroll
            for (int i = 0; i < 4; i++) {
                float4 s = make_float4(0.f, 0.f, 0.f, 0.f);
#pragma unroll
                for (int msx = 0; msx < 8; msx++) {
                    const float4* gp = (const float4*)(g_xg2p + (size_t)msx * BB * NN * 64 + rowoff);
                    float4 a = gp[l2 * 4 + i];
                    s.x += a.x; s.y += a.y; s.z += a.z; s.w += a.w;
                }
                *(float4*)&sxg[bb][64 + (l2 * 4 + i) * 4] = s;
            }
        }
    }
    __syncthreads();

    int bb = tid >> 3, og = tid & 7;    // og covers o = og*8 .. og*8+7
    ULL acc0 = 0ULL, acc1 = 0ULL, acc2v = 0ULL, acc3 = 0ULL;
#pragma unroll
    for (int e = 0; e < 16; e++) {
        float ev = semb[e];
        ULL ep = pack2(ev, ev);
        ulonglong2 b01 = *(const ulonglong2*)&sbp[e * 64 + og * 8];
        ulonglong2 b23 = *(const ulonglong2*)&sbp[e * 64 + og * 8 + 4];
        fma2(acc0, ep, b01.x); fma2(acc1, ep, b01.y);
        fma2(acc2v, ep, b23.x); fma2(acc3, ep, b23.y);
    }
#pragma unroll 4
    for (int kc = 0; kc < 128; kc++) {
        float xv = sxg[bb][kc];
        ULL xp = pack2(xv, xv);
        ulonglong2 w01 = *(const ulonglong2*)&sW[kc * 64 + og * 8];
        ulonglong2 w23 = *(const ulonglong2*)&sW[kc * 64 + og * 8 + 4];
        fma2(acc0, xp, w01.x); fma2(acc1, xp, w01.y);
        fma2(acc2v, xp, w23.x); fma2(acc3, xp, w23.y);
    }
    float2 r0 = unpack2(acc0), r1 = unpack2(acc1);
    float2 r2 = unpack2(acc2v), r3 = unpack2(acc3);
    size_t rowoff = ((size_t)bb * NN + n) * 64;
    *(float4*)&out[rowoff + og * 8]     = make_float4(r0.x, r0.y, r1.x, r1.y);
    *(float4*)&out[rowoff + og * 8 + 4] = make_float4(r2.x, r2.y, r3.x, r3.y);
}

// ---------------- launch (serial, proven order) -------------------------------
extern "C" void kernel_launch(void* const* d_in, const int* in_sizes, int n_in,
                              void* d_out, int out_size)
{
    const float* x    = (const float*)d_in[0];
    const float* emb0 = (const float*)d_in[1];
    const float* emb1 = (const float*)d_in[2];
    const float* w1   = (const float*)d_in[3];
    const float* b1   = (const float*)d_in[4];
    const float* w2   = (const float*)d_in[5];
    const float* b2   = (const float*)d_in[6];
    const float* w3   = (const float*)d_in[7];
    const float* b3   = (const float*)d_in[8];
    const float* wp   = (const float*)d_in[9];
    const float* bp   = (const float*)d_in[10];
    float* out = (float*)d_out;

    (void)in_sizes; (void)n_in; (void)out_size;

    const int smem_k_xg2 = (128 * 64 + 64 * 64 + 16 * 128 + 16 * 64) * 4;  // 61440 B
    cudaFuncSetAttribute(k_xg2, cudaFuncAttributeMaxDynamicSharedMemorySize, smem_k_xg2);

    k_nodevec<<<(BB * NN) / 256, 256>>>(x, emb0, w1, b1, w2, b2, w3, b3);
    k_wpre<<<dim3(8, 128), 256>>>(emb1, wp);
    k_dinv<<<dim3(8, 16, 8), 128>>>();
    k_dred<<<(BB * NN) / 256, 256>>>();
    k_xg2<<<dim3(16, 16, 8), 128, smem_k_xg2>>>(x);
    k_out<<<NN, 128>>>(x, emb1, bp, out);
}

// round 16
// speedup vs baseline: 1.0895x; 1.0895x over previous
#include <cuda_runtime.h>
#include <math.h>

#define BB 16
#define NN 2048
#define CC 64
#define EE 16
#define OO 64
// K=2, C=64 -> KC = 128

typedef unsigned long long ULL;

// ---------------- f32x2 packed-FMA helpers (sm_100+) -------------------------
__device__ __forceinline__ ULL pack2(float a, float b) {
    ULL r;
    asm("mov.b64 %0, {%1, %2};" : "=l"(r) : "f"(a), "f"(b));
    return r;
}
__device__ __forceinline__ void fma2(ULL& d, ULL a, ULL b) {
    asm("fma.rn.f32x2 %0, %1, %2, %0;" : "+l"(d) : "l"(a), "l"(b));
}
__device__ __forceinline__ float2 unpack2(ULL v) {
    float x, y;
    asm("mov.b64 {%0, %1}, %2;" : "=f"(x), "=f"(y) : "l"(v));
    return make_float2(x, y);
}

// ---------------- scratch (device globals; no allocations allowed) ----------
__device__ float g_nodevec[BB * NN * EE];                    // 2 MB
__device__ float g_dsum[8 * BB * NN];                        // 1 MB (8 m-split partials)
__device__ float g_dinv[BB * NN];                            // 128 KB (reduced rsqrt)
__device__ float g_W[(size_t)NN * 128 * 64];                 // 64 MB (n, kc, o)
__device__ float g_xg2p[(size_t)8 * BB * NN * CC];           // 64 MB (8 m-split partials)

// ---------------- K1: hyper-MLP -> nodevec ---------------------------------
__global__ void k_nodevec(const float* __restrict__ x, const float* __restrict__ emb0,
                          const float* __restrict__ w1, const float* __restrict__ b1,
                          const float* __restrict__ w2, const float* __restrict__ b2,
                          const float* __restrict__ w3, const float* __restrict__ b3)
{
    __shared__ float s_w1[1024];
    __shared__ float s_b1[16], s_w2[32], s_b2[2], s_w3[32], s_b3[16];
    int tid = threadIdx.x;
    for (int i = tid; i < 1024; i += 256) s_w1[i] = w1[i];
    if (tid < 16) s_b1[tid] = b1[tid];
    if (tid < 32) s_w2[tid] = w2[tid];
    if (tid < 2)  s_b2[tid] = b2[tid];
    if (tid >= 32 && tid < 64) s_w3[tid - 32] = w3[tid - 32];
    if (tid >= 64 && tid < 80) s_b3[tid - 64] = b3[tid - 64];
    __syncthreads();

    int row = blockIdx.x * 256 + tid;
    const float4* xr = (const float4*)(x + (size_t)row * 64);
    float xv[64];
#pragma unroll
    for (int i = 0; i < 16; i++) {
        float4 t = xr[i];
        xv[4*i] = t.x; xv[4*i+1] = t.y; xv[4*i+2] = t.z; xv[4*i+3] = t.w;
    }
    float h[16];
#pragma unroll
    for (int j = 0; j < 16; j++) h[j] = s_b1[j];
#pragma unroll
    for (int c = 0; c < 64; c++) {
        float xc = xv[c];
#pragma unroll
        for (int j = 0; j < 16; j++) h[j] = fmaf(xc, s_w1[c * 16 + j], h[j]);
    }
#pragma unroll
    for (int j = 0; j < 16; j++) h[j] = 1.0f / (1.0f + expf(-h[j]));

    float h2[2];
#pragma unroll
    for (int m = 0; m < 2; m++) {
        float a = s_b2[m];
#pragma unroll
        for (int j = 0; j < 16; j++) a = fmaf(h[j], s_w2[j * 2 + m], a);
        h2[m] = 1.0f / (1.0f + expf(-a));
    }

    float filt[16];
#pragma unroll
    for (int e = 0; e < 16; e++)
        filt[e] = s_b3[e] + h2[0] * s_w3[e] + h2[1] * s_w3[16 + e];

    const float4* e0p = (const float4*)(emb0 + (size_t)row * 16);
    float4* nvout = (float4*)(g_nodevec + (size_t)row * 16);
#pragma unroll
    for (int q = 0; q < 4; q++) {
        float4 ev = e0p[q];
        float4 r;
        r.x = tanhf(ev.x * filt[4*q + 0]);
        r.y = tanhf(ev.y * filt[4*q + 1]);
        r.z = tanhf(ev.z * filt[4*q + 2]);
        r.w = tanhf(ev.w * filt[4*q + 3]);
        nvout[q] = r;
    }
}

// ---------------- K2: W[n,kc,o] = sum_e emb1[n,e] * wp[e,kc,o] (f32x2) -------
__global__ void k_wpre(const float* __restrict__ emb1, const float* __restrict__ wp)
{
    __shared__ float s_emb[256];
    int tid = threadIdx.x;
    int n0 = blockIdx.y * 16;
    s_emb[tid] = emb1[(size_t)n0 * 16 + tid];
    __syncthreads();

    int r4 = blockIdx.x * 256 + tid;
    const float4* wp4 = (const float4*)wp;
    ulonglong2 wv[16];
#pragma unroll
    for (int e = 0; e < 16; e++) {
        float4 t = wp4[(size_t)e * 2048 + r4];
        wv[e].x = pack2(t.x, t.y);
        wv[e].y = pack2(t.z, t.w);
    }

#pragma unroll 4
    for (int nn = 0; nn < 16; nn++) {
        ULL a0 = 0ULL, a1 = 0ULL;
#pragma unroll
        for (int e = 0; e < 16; e++) {
            float s = s_emb[nn * 16 + e];
            ULL sp = pack2(s, s);
            fma2(a0, sp, wv[e].x);
            fma2(a1, sp, wv[e].y);
        }
        float2 r0 = unpack2(a0), r1 = unpack2(a1);
        ((float4*)g_W)[(size_t)(n0 + nn) * 2048 + r4] =
            make_float4(r0.x, r0.y, r1.x, r1.y);
    }
}

// ---------------- K3: partial dsum[ms,b,n], 2 n-rows per thread -------------
// grid (8, 16, 8), 128 threads. Rows n0+tid, n0+128+tid; 256 m per block.
__global__ void __launch_bounds__(128) k_dinv()
{
    __shared__ float s_vmT[16][128];
    int tid = threadIdx.x;
    int b = blockIdx.y;
    int ms = blockIdx.z;
    int n0 = blockIdx.x * 256;
    const float* nvb = g_nodevec + (size_t)b * NN * 16;

    ULL vnd[2][16];
#pragma unroll
    for (int r = 0; r < 2; r++) {
        const float4* p = (const float4*)(nvb + (size_t)(n0 + r * 128 + tid) * 16);
#pragma unroll
        for (int q = 0; q < 4; q++) {
            float4 t = p[q];
            vnd[r][4*q+0] = pack2(t.x, t.x);
            vnd[r][4*q+1] = pack2(t.y, t.y);
            vnd[r][4*q+2] = pack2(t.z, t.z);
            vnd[r][4*q+3] = pack2(t.w, t.w);
        }
    }
    float sacc0 = 0.f, sacc1 = 0.f;
    for (int mt = 0; mt < 2; mt++) {
        int m0 = ms * 256 + mt * 128;
        __syncthreads();
        {
            const float4* q = (const float4*)(nvb + (size_t)(m0 + tid) * 16);
#pragma unroll
            for (int i = 0; i < 4; i++) {
                float4 t = q[i];
                s_vmT[4*i+0][tid] = t.x; s_vmT[4*i+1][tid] = t.y;
                s_vmT[4*i+2][tid] = t.z; s_vmT[4*i+3][tid] = t.w;
            }
        }
        __syncthreads();
#pragma unroll 2
        for (int mm = 0; mm < 128; mm += 4) {
            ULL d00 = 0ULL, d01 = 0ULL, d10 = 0ULL, d11 = 0ULL;
#pragma unroll
            for (int e = 0; e < 16; e++) {
                ulonglong2 v = *(const ulonglong2*)&s_vmT[e][mm];
                fma2(d00, vnd[0][e], v.x); fma2(d01, vnd[0][e], v.y);
                fma2(d10, vnd[1][e], v.x); fma2(d11, vnd[1][e], v.y);
            }
            float2 a0 = unpack2(d00), a1 = unpack2(d01);
            float2 b0 = unpack2(d10), b1 = unpack2(d11);
            sacc0 += (fmaxf(a0.x, 0.f) + fmaxf(a0.y, 0.f)) +
                     (fmaxf(a1.x, 0.f) + fmaxf(a1.y, 0.f));
            sacc1 += (fmaxf(b0.x, 0.f) + fmaxf(b0.y, 0.f)) +
                     (fmaxf(b1.x, 0.f) + fmaxf(b1.y, 0.f));
        }
    }
    size_t base = ((size_t)ms * BB + b) * NN + n0 + tid;
    g_dsum[base] = sacc0;
    g_dsum[base + 128] = sacc1;
}

// ---------------- K3b: reduce dsum partials -> g_dinv = rsqrt(sum) ----------
__global__ void k_dred()
{
    int i = blockIdx.x * 256 + threadIdx.x;     // 0 .. BB*NN-1
    float s = 0.f;
#pragma unroll
    for (int p = 0; p < 8; p++) s += g_dsum[(size_t)p * BB * NN + i];
    g_dinv[i] = rsqrtf(s);
}

// ---------------- K4: x_g2 partials: L @ x (R6 best config) ------------------
// 128 threads; grid (16 nt, 16 b, 8 ms). m-chunk = 64; 4 mi per block.
// smem 60KB, <=170 regs -> 3 CTAs/SM. Thread tile: 8 rows x 8 cols.
// sA swizzle: A[row][col] at sA[row*64 + (((col>>2) ^ ((row>>2)&3))<<2) + (col&3)].
__global__ void __launch_bounds__(128, 3) k_xg2(const float* __restrict__ x)
{
    extern __shared__ float sm[];
    float* sA   = sm;                    // 128*64 swizzled (32KB)
    float* sXm  = sA + 128 * 64;         // 64*64 (16KB)
    float* sVnT = sXm + 64 * 64;         // 16*128 [e][n] (8KB)
    float* sVmT = sVnT + 16 * 128;       // 16*64 [e][m] (4KB)

    int tid = threadIdx.x;
    int nt = blockIdx.x, b = blockIdx.y, ms = blockIdx.z;
    int n0 = nt * 128;
    const float* nvb = g_nodevec + (size_t)b * NN * 16;
    const float* dvb = g_dinv + (size_t)b * NN;

    int rgrp = tid >> 3;                 // 0..15 -> rows rgrp*8 .. +8
    int cgrp = tid & 7;
    int row0 = rgrp * 8;
    int key0 = (rgrp * 2) & 3;           // (row>>2)&3 for rows row0..row0+3
    int key1 = (rgrp * 2 + 1) & 3;       // for rows row0+4..row0+7
    int c0 = cgrp * 4, c1 = 32 + cgrp * 4;

    // load VnT (d-scaled), once: 1 row per thread
    {
        int r = tid;
        float dv = dvb[n0 + r];
        const float4* p = (const float4*)(nvb + (size_t)(n0 + r) * 16);
#pragma unroll
        for (int q = 0; q < 4; q++) {
            float4 t = p[q];
            sVnT[(q*4+0)*128 + r] = t.x*dv; sVnT[(q*4+1)*128 + r] = t.y*dv;
            sVnT[(q*4+2)*128 + r] = t.z*dv; sVnT[(q*4+3)*128 + r] = t.w*dv;
        }
    }

    ULL acc[8][4];
#pragma unroll
    for (int i = 0; i < 8; i++)
#pragma unroll
        for (int j = 0; j < 4; j++) acc[i][j] = 0ULL;

    for (int mi = 0; mi < 4; mi++) {
        int m0 = ms * 256 + mi * 64;
        __syncthreads();
        // stage VmT (d-scaled): 64 rows, 2 threads/row
        {
            int r = tid >> 1, half = tid & 1;
            float dv = dvb[m0 + r];
            const float4* p = (const float4*)(nvb + (size_t)(m0 + r) * 16 + half * 8);
            float4 t0 = p[0], t1 = p[1];
            int e0 = half * 8;
            sVmT[(e0+0)*64 + r] = t0.x*dv; sVmT[(e0+1)*64 + r] = t0.y*dv;
            sVmT[(e0+2)*64 + r] = t0.z*dv; sVmT[(e0+3)*64 + r] = t0.w*dv;
            sVmT[(e0+4)*64 + r] = t1.x*dv; sVmT[(e0+5)*64 + r] = t1.y*dv;
            sVmT[(e0+6)*64 + r] = t1.z*dv; sVmT[(e0+7)*64 + r] = t1.w*dv;
        }
        // stage X chunk: 64x64 = 1024 float4, 8 per thread
        {
            const float4* xp = (const float4*)(x + ((size_t)b * NN + m0) * 64);
            float4* xs = (float4*)sXm;
#pragma unroll
            for (int i = 0; i < 8; i++) xs[tid + i * 128] = xp[tid + i * 128];
        }
        __syncthreads();

        // ---- Phase A: A = relu((d.Vn)(d.Vm)^T) -> swizzled sA (4-row passes)
#pragma unroll
        for (int pass = 0; pass < 2; pass++) {
            int prow = row0 + pass * 4;
            int key = pass ? key1 : key0;
            int l0p = (cgrp ^ key) << 2;
            int l1p = ((8 + cgrp) ^ key) << 2;
            ULL pa[4][4];
#pragma unroll
            for (int i = 0; i < 4; i++)
#pragma unroll
                for (int j = 0; j < 4; j++) pa[i][j] = 0ULL;
#pragma unroll
            for (int e = 0; e < 16; e++) {
                float4 vn = *(const float4*)&sVnT[e * 128 + prow];
                ulonglong2 va = *(const ulonglong2*)&sVmT[e * 64 + c0];
                ulonglong2 vb = *(const ulonglong2*)&sVmT[e * 64 + c1];
                float vv[4] = {vn.x, vn.y, vn.z, vn.w};
#pragma unroll
                for (int i = 0; i < 4; i++) {
                    ULL ad = pack2(vv[i], vv[i]);
                    fma2(pa[i][0], ad, va.x); fma2(pa[i][1], ad, va.y);
                    fma2(pa[i][2], ad, vb.x); fma2(pa[i][3], ad, vb.y);
                }
            }
#pragma unroll
            for (int i = 0; i < 4; i++) {
                int row = prow + i;
                float2 p0 = unpack2(pa[i][0]);
                float2 p1 = unpack2(pa[i][1]);
                float2 p2 = unpack2(pa[i][2]);
                float2 p3 = unpack2(pa[i][3]);
                float4 o0 = make_float4(fmaxf(p0.x, 0.f), fmaxf(p0.y, 0.f),
                                        fmaxf(p1.x, 0.f), fmaxf(p1.y, 0.f));
                float4 o1 = make_float4(fmaxf(p2.x, 0.f), fmaxf(p2.y, 0.f),
                                        fmaxf(p3.x, 0.f), fmaxf(p3.y, 0.f));
                *(float4*)&sA[row * 64 + l0p] = o0;
                *(float4*)&sA[row * 64 + l1p] = o1;
            }
        }
        __syncthreads();

        // ---- Phase B: acc += A @ Xm (8 rows x 8 cols per thread) -----------
#pragma unroll 2
        for (int kf4 = 0; kf4 < 16; kf4++) {
            int laneA = ((kf4 ^ key0) << 2);
            int laneB = ((kf4 ^ key1) << 2);
            float4 a[8];
#pragma unroll
            for (int i = 0; i < 4; i++)
                a[i] = *(const float4*)&sA[(row0 + i) * 64 + laneA];
#pragma unroll
            for (int i = 4; i < 8; i++)
                a[i] = *(const float4*)&sA[(row0 + i) * 64 + laneB];
#pragma unroll
            for (int kk = 0; kk < 4; kk++) {
                int k = kf4 * 4 + kk;
                ulonglong2 xa = *(const ulonglong2*)&sXm[k * 64 + c0];
                ulonglong2 xb = *(const ulonglong2*)&sXm[k * 64 + c1];
#pragma unroll
                for (int i = 0; i < 8; i++) {
                    float av = (kk == 0) ? a[i].x : (kk == 1) ? a[i].y
                             : (kk == 2) ? a[i].z : a[i].w;
                    ULL ad = pack2(av, av);
                    fma2(acc[i][0], ad, xa.x);
                    fma2(acc[i][1], ad, xa.y);
                    fma2(acc[i][2], ad, xb.x);
                    fma2(acc[i][3], ad, xb.y);
                }
            }
        }
    }

    // epilogue: store partial (d_n already folded in)
    float* op = g_xg2p + (((size_t)ms * BB + b) * NN + n0) * 64;
#pragma unroll
    for (int i = 0; i < 8; i++) {
        int row = row0 + i;
        float2 q0 = unpack2(acc[i][0]);
        float2 q1 = unpack2(acc[i][1]);
        float2 q2 = unpack2(acc[i][2]);
        float2 q3 = unpack2(acc[i][3]);
        *(float4*)&op[(size_t)row * 64 + c0] = make_float4(q0.x, q0.y, q1.x, q1.y);
        *(float4*)&op[(size_t)row * 64 + c1] = make_float4(q2.x, q2.y, q3.x, q3.y);
    }
}

// ---------------- K5: out = x_g @ W[n] + bias (o-pair f32x2, R9/R13 proven) --
__global__ void k_out(const float* __restrict__ x, const float* __restrict__ emb1,
                      const float* __restrict__ bias_pool, float* __restrict__ out)
{
    __shared__ float sW[128 * 64];
    __shared__ float sxg[16][128];
    __shared__ float sbp[16 * 64];
    __shared__ float semb[16];
    int n = blockIdx.x;
    int tid = threadIdx.x;
    {
        const float4* wp = (const float4*)(g_W + (size_t)n * 8192);
        float4* sW4 = (float4*)sW;
#pragma unroll
        for (int i = 0; i < 8; i++) sW4[tid + i * 256] = wp[tid + i * 256];
    }
#pragma unroll
    for (int i = 0; i < 4; i++) sbp[tid + i * 256] = bias_pool[tid + i * 256];
    if (tid < 16) semb[tid] = emb1[(size_t)n * 16 + tid];
    {
        int bb = tid >> 4, lane = tid & 15;
        size_t rowoff = ((size_t)bb * NN + n) * 64;
        if (lane < 8) {
            const float4* xp = (const float4*)(x + rowoff);
            *(float4*)&sxg[bb][lane * 8]     = xp[lane * 2];
            *(float4*)&sxg[bb][lane * 8 + 4] = xp[lane * 2 + 1];
        } else {
            int l2 = lane - 8;
            float4 s0 = make_float4(0.f, 0.f, 0.f, 0.f);
            float4 s1 = make_float4(0.f, 0.f, 0.f, 0.f);
#pragma unroll
            for (int msx = 0; msx < 8; msx++) {
                const float4* gp = (const float4*)(g_xg2p + (size_t)msx * BB * NN * 64 + rowoff);
                float4 a = gp[l2 * 2], c = gp[l2 * 2 + 1];
                s0.x += a.x; s0.y += a.y; s0.z += a.z; s0.w += a.w;
                s1.x += c.x; s1.y += c.y; s1.z += c.z; s1.w += c.w;
            }
            *(float4*)&sxg[bb][64 + l2 * 8]     = s0;
            *(float4*)&sxg[bb][64 + l2 * 8 + 4] = s1;
        }
    }
    __syncthreads();

    int bb = tid >> 4, og = tid & 15;
    float4 accb = make_float4(0.f, 0.f, 0.f, 0.f);
#pragma unroll
    for (int e = 0; e < 16; e++) {
        float ev = semb[e];
        float4 bp4 = *(const float4*)&sbp[e * 64 + og * 4];
        accb.x = fmaf(ev, bp4.x, accb.x);
        accb.y = fmaf(ev, bp4.y, accb.y);
        accb.z = fmaf(ev, bp4.z, accb.z);
        accb.w = fmaf(ev, bp4.w, accb.w);
    }
    ULL acc0 = pack2(accb.x, accb.y);
    ULL acc1 = pack2(accb.z, accb.w);
#pragma unroll 4
    for (int kc = 0; kc < 128; kc++) {
        float xv = sxg[bb][kc];
        ULL xp = pack2(xv, xv);
        ulonglong2 w = *(const ulonglong2*)&sW[kc * 64 + og * 4];
        fma2(acc0, xp, w.x);
        fma2(acc1, xp, w.y);
    }
    float2 r0 = unpack2(acc0);
    float2 r1 = unpack2(acc1);
    size_t rowoff = ((size_t)bb * NN + n) * 64;
    *(float4*)&out[rowoff + og * 4] = make_float4(r0.x, r0.y, r1.x, r1.y);
}

// ---------------- launch (serial, proven order) -------------------------------
extern "C" void kernel_launch(void* const* d_in, const int* in_sizes, int n_in,
                              void* d_out, int out_size)
{
    const float* x    = (const float*)d_in[0];
    const float* emb0 = (const float*)d_in[1];
    const float* emb1 = (const float*)d_in[2];
    const float* w1   = (const float*)d_in[3];
    const float* b1   = (const float*)d_in[4];
    const float* w2   = (const float*)d_in[5];
    const float* b2   = (const float*)d_in[6];
    const float* w3   = (const float*)d_in[7];
    const float* b3   = (const float*)d_in[8];
    const float* wp   = (const float*)d_in[9];
    const float* bp   = (const float*)d_in[10];
    float* out = (float*)d_out;

    (void)in_sizes; (void)n_in; (void)out_size;

    const int smem_k_xg2 = (128 * 64 + 64 * 64 + 16 * 128 + 16 * 64) * 4;  // 61440 B
    cudaFuncSetAttribute(k_xg2, cudaFuncAttributeMaxDynamicSharedMemorySize, smem_k_xg2);

    k_nodevec<<<(BB * NN) / 256, 256>>>(x, emb0, w1, b1, w2, b2, w3, b3);
    k_wpre<<<dim3(8, 128), 256>>>(emb1, wp);
    k_dinv<<<dim3(8, 16, 8), 128>>>();
    k_dred<<<(BB * NN) / 256, 256>>>();
    k_xg2<<<dim3(16, 16, 8), 128, smem_k_xg2>>>(x);
    k_out<<<NN, 256>>>(x, emb1, bp, out);
}

// round 17
// speedup vs baseline: 1.0925x; 1.0027x over previous
#include <cuda_runtime.h>
#include <math.h>

#define BB 16
#define NN 2048
#define CC 64
#define EE 16
#define OO 64
// K=2, C=64 -> KC = 128

typedef unsigned long long ULL;

// ---------------- f32x2 packed-FMA helpers (sm_100+) -------------------------
__device__ __forceinline__ ULL pack2(float a, float b) {
    ULL r;
    asm("mov.b64 %0, {%1, %2};" : "=l"(r) : "f"(a), "f"(b));
    return r;
}
__device__ __forceinline__ void fma2(ULL& d, ULL a, ULL b) {
    asm("fma.rn.f32x2 %0, %1, %2, %0;" : "+l"(d) : "l"(a), "l"(b));
}
__device__ __forceinline__ float2 unpack2(ULL v) {
    float x, y;
    asm("mov.b64 {%0, %1}, %2;" : "=f"(x), "=f"(y) : "l"(v));
    return make_float2(x, y);
}

// ---------------- scratch (device globals; no allocations allowed) ----------
__device__ float g_nodevec[BB * NN * EE];                    // 2 MB
__device__ float g_dsum[8 * BB * NN];                        // 1 MB (8 m-split partials)
__device__ float g_dinv[BB * NN];                            // 128 KB (reduced rsqrt)
__device__ float g_W[(size_t)NN * 128 * 64];                 // 64 MB (n, kc, o)
__device__ float g_xg2p[(size_t)8 * BB * NN * CC];           // 64 MB (8 m-split partials)

// ---------------- K1: hyper-MLP -> nodevec ---------------------------------
__global__ void k_nodevec(const float* __restrict__ x, const float* __restrict__ emb0,
                          const float* __restrict__ w1, const float* __restrict__ b1,
                          const float* __restrict__ w2, const float* __restrict__ b2,
                          const float* __restrict__ w3, const float* __restrict__ b3)
{
    __shared__ float s_w1[1024];
    __shared__ float s_b1[16], s_w2[32], s_b2[2], s_w3[32], s_b3[16];
    int tid = threadIdx.x;
    for (int i = tid; i < 1024; i += 256) s_w1[i] = w1[i];
    if (tid < 16) s_b1[tid] = b1[tid];
    if (tid < 32) s_w2[tid] = w2[tid];
    if (tid < 2)  s_b2[tid] = b2[tid];
    if (tid >= 32 && tid < 64) s_w3[tid - 32] = w3[tid - 32];
    if (tid >= 64 && tid < 80) s_b3[tid - 64] = b3[tid - 64];
    __syncthreads();

    int row = blockIdx.x * 256 + tid;
    const float4* xr = (const float4*)(x + (size_t)row * 64);
    float xv[64];
#pragma unroll
    for (int i = 0; i < 16; i++) {
        float4 t = xr[i];
        xv[4*i] = t.x; xv[4*i+1] = t.y; xv[4*i+2] = t.z; xv[4*i+3] = t.w;
    }
    float h[16];
#pragma unroll
    for (int j = 0; j < 16; j++) h[j] = s_b1[j];
#pragma unroll
    for (int c = 0; c < 64; c++) {
        float xc = xv[c];
#pragma unroll
        for (int j = 0; j < 16; j++) h[j] = fmaf(xc, s_w1[c * 16 + j], h[j]);
    }
#pragma unroll
    for (int j = 0; j < 16; j++) h[j] = 1.0f / (1.0f + expf(-h[j]));

    float h2[2];
#pragma unroll
    for (int m = 0; m < 2; m++) {
        float a = s_b2[m];
#pragma unroll
        for (int j = 0; j < 16; j++) a = fmaf(h[j], s_w2[j * 2 + m], a);
        h2[m] = 1.0f / (1.0f + expf(-a));
    }

    float filt[16];
#pragma unroll
    for (int e = 0; e < 16; e++)
        filt[e] = s_b3[e] + h2[0] * s_w3[e] + h2[1] * s_w3[16 + e];

    const float4* e0p = (const float4*)(emb0 + (size_t)row * 16);
    float4* nvout = (float4*)(g_nodevec + (size_t)row * 16);
#pragma unroll
    for (int q = 0; q < 4; q++) {
        float4 ev = e0p[q];
        float4 r;
        r.x = tanhf(ev.x * filt[4*q + 0]);
        r.y = tanhf(ev.y * filt[4*q + 1]);
        r.z = tanhf(ev.z * filt[4*q + 2]);
        r.w = tanhf(ev.w * filt[4*q + 3]);
        nvout[q] = r;
    }
}

// ---------------- K2: W[n,kc,o] = sum_e emb1[n,e] * wp[e,kc,o] (f32x2) -------
__global__ void k_wpre(const float* __restrict__ emb1, const float* __restrict__ wp)
{
    __shared__ float s_emb[256];
    int tid = threadIdx.x;
    int n0 = blockIdx.y * 16;
    s_emb[tid] = emb1[(size_t)n0 * 16 + tid];
    __syncthreads();

    int r4 = blockIdx.x * 256 + tid;
    const float4* wp4 = (const float4*)wp;
    ulonglong2 wv[16];
#pragma unroll
    for (int e = 0; e < 16; e++) {
        float4 t = wp4[(size_t)e * 2048 + r4];
        wv[e].x = pack2(t.x, t.y);
        wv[e].y = pack2(t.z, t.w);
    }

#pragma unroll 4
    for (int nn = 0; nn < 16; nn++) {
        ULL a0 = 0ULL, a1 = 0ULL;
#pragma unroll
        for (int e = 0; e < 16; e++) {
            float s = s_emb[nn * 16 + e];
            ULL sp = pack2(s, s);
            fma2(a0, sp, wv[e].x);
            fma2(a1, sp, wv[e].y);
        }
        float2 r0 = unpack2(a0), r1 = unpack2(a1);
        ((float4*)g_W)[(size_t)(n0 + nn) * 2048 + r4] =
            make_float4(r0.x, r0.y, r1.x, r1.y);
    }
}

// ---------------- K3: partial dsum[ms,b,n], 2 n-rows per thread -------------
// grid (8, 16, 8), 128 threads. Rows n0+tid, n0+128+tid; 256 m per block.
__global__ void __launch_bounds__(128) k_dinv()
{
    __shared__ float s_vmT[16][128];
    int tid = threadIdx.x;
    int b = blockIdx.y;
    int ms = blockIdx.z;
    int n0 = blockIdx.x * 256;
    const float* nvb = g_nodevec + (size_t)b * NN * 16;

    ULL vnd[2][16];
#pragma unroll
    for (int r = 0; r < 2; r++) {
        const float4* p = (const float4*)(nvb + (size_t)(n0 + r * 128 + tid) * 16);
#pragma unroll
        for (int q = 0; q < 4; q++) {
            float4 t = p[q];
            vnd[r][4*q+0] = pack2(t.x, t.x);
            vnd[r][4*q+1] = pack2(t.y, t.y);
            vnd[r][4*q+2] = pack2(t.z, t.z);
            vnd[r][4*q+3] = pack2(t.w, t.w);
        }
    }
    float sacc0 = 0.f, sacc1 = 0.f;
    for (int mt = 0; mt < 2; mt++) {
        int m0 = ms * 256 + mt * 128;
        __syncthreads();
        {
            const float4* q = (const float4*)(nvb + (size_t)(m0 + tid) * 16);
#pragma unroll
            for (int i = 0; i < 4; i++) {
                float4 t = q[i];
                s_vmT[4*i+0][tid] = t.x; s_vmT[4*i+1][tid] = t.y;
                s_vmT[4*i+2][tid] = t.z; s_vmT[4*i+3][tid] = t.w;
            }
        }
        __syncthreads();
#pragma unroll 2
        for (int mm = 0; mm < 128; mm += 4) {
            ULL d00 = 0ULL, d01 = 0ULL, d10 = 0ULL, d11 = 0ULL;
#pragma unroll
            for (int e = 0; e < 16; e++) {
                ulonglong2 v = *(const ulonglong2*)&s_vmT[e][mm];
                fma2(d00, vnd[0][e], v.x); fma2(d01, vnd[0][e], v.y);
                fma2(d10, vnd[1][e], v.x); fma2(d11, vnd[1][e], v.y);
            }
            float2 a0 = unpack2(d00), a1 = unpack2(d01);
            float2 b0 = unpack2(d10), b1 = unpack2(d11);
            sacc0 += (fmaxf(a0.x, 0.f) + fmaxf(a0.y, 0.f)) +
                     (fmaxf(a1.x, 0.f) + fmaxf(a1.y, 0.f));
            sacc1 += (fmaxf(b0.x, 0.f) + fmaxf(b0.y, 0.f)) +
                     (fmaxf(b1.x, 0.f) + fmaxf(b1.y, 0.f));
        }
    }
    size_t base = ((size_t)ms * BB + b) * NN + n0 + tid;
    g_dsum[base] = sacc0;
    g_dsum[base + 128] = sacc1;
}

// ---------------- K3b: reduce dsum partials -> g_dinv = rsqrt(sum) ----------
__global__ void k_dred()
{
    int i = blockIdx.x * 256 + threadIdx.x;     // 0 .. BB*NN-1
    float s = 0.f;
#pragma unroll
    for (int p = 0; p < 8; p++) s += g_dsum[(size_t)p * BB * NN + i];
    g_dinv[i] = rsqrtf(s);
}

// ---------------- K4: x_g2 partials: L @ x (R6 best config) ------------------
// 128 threads; grid (16 nt, 16 b, 8 ms). m-chunk = 64; 4 mi per block.
// smem 60KB, <=170 regs -> 3 CTAs/SM. Thread tile: 8 rows x 8 cols.
// sA swizzle: A[row][col] at sA[row*64 + (((col>>2) ^ ((row>>2)&3))<<2) + (col&3)].
__global__ void __launch_bounds__(128, 3) k_xg2(const float* __restrict__ x)
{
    extern __shared__ float sm[];
    float* sA   = sm;                    // 128*64 swizzled (32KB)
    float* sXm  = sA + 128 * 64;         // 64*64 (16KB)
    float* sVnT = sXm + 64 * 64;         // 16*128 [e][n] (8KB)
    float* sVmT = sVnT + 16 * 128;       // 16*64 [e][m] (4KB)

    int tid = threadIdx.x;
    int nt = blockIdx.x, b = blockIdx.y, ms = blockIdx.z;
    int n0 = nt * 128;
    const float* nvb = g_nodevec + (size_t)b * NN * 16;
    const float* dvb = g_dinv + (size_t)b * NN;

    int rgrp = tid >> 3;                 // 0..15 -> rows rgrp*8 .. +8
    int cgrp = tid & 7;
    int row0 = rgrp * 8;
    int key0 = (rgrp * 2) & 3;           // (row>>2)&3 for rows row0..row0+3
    int key1 = (rgrp * 2 + 1) & 3;       // for rows row0+4..row0+7
    int c0 = cgrp * 4, c1 = 32 + cgrp * 4;

    // load VnT (d-scaled), once: 1 row per thread
    {
        int r = tid;
        float dv = dvb[n0 + r];
        const float4* p = (const float4*)(nvb + (size_t)(n0 + r) * 16);
#pragma unroll
        for (int q = 0; q < 4; q++) {
            float4 t = p[q];
            sVnT[(q*4+0)*128 + r] = t.x*dv; sVnT[(q*4+1)*128 + r] = t.y*dv;
            sVnT[(q*4+2)*128 + r] = t.z*dv; sVnT[(q*4+3)*128 + r] = t.w*dv;
        }
    }

    ULL acc[8][4];
#pragma unroll
    for (int i = 0; i < 8; i++)
#pragma unroll
        for (int j = 0; j < 4; j++) acc[i][j] = 0ULL;

    for (int mi = 0; mi < 4; mi++) {
        int m0 = ms * 256 + mi * 64;
        __syncthreads();
        // stage VmT (d-scaled): 64 rows, 2 threads/row
        {
            int r = tid >> 1, half = tid & 1;
            float dv = dvb[m0 + r];
            const float4* p = (const float4*)(nvb + (size_t)(m0 + r) * 16 + half * 8);
            float4 t0 = p[0], t1 = p[1];
            int e0 = half * 8;
            sVmT[(e0+0)*64 + r] = t0.x*dv; sVmT[(e0+1)*64 + r] = t0.y*dv;
            sVmT[(e0+2)*64 + r] = t0.z*dv; sVmT[(e0+3)*64 + r] = t0.w*dv;
            sVmT[(e0+4)*64 + r] = t1.x*dv; sVmT[(e0+5)*64 + r] = t1.y*dv;
            sVmT[(e0+6)*64 + r] = t1.z*dv; sVmT[(e0+7)*64 + r] = t1.w*dv;
        }
        // stage X chunk: 64x64 = 1024 float4, 8 per thread
        {
            const float4* xp = (const float4*)(x + ((size_t)b * NN + m0) * 64);
            float4* xs = (float4*)sXm;
#pragma unroll
            for (int i = 0; i < 8; i++) xs[tid + i * 128] = xp[tid + i * 128];
        }
        __syncthreads();

        // ---- Phase A: A = relu((d.Vn)(d.Vm)^T) -> swizzled sA (4-row passes)
#pragma unroll
        for (int pass = 0; pass < 2; pass++) {
            int prow = row0 + pass * 4;
            int key = pass ? key1 : key0;
            int l0p = (cgrp ^ key) << 2;
            int l1p = ((8 + cgrp) ^ key) << 2;
            ULL pa[4][4];
#pragma unroll
            for (int i = 0; i < 4; i++)
#pragma unroll
                for (int j = 0; j < 4; j++) pa[i][j] = 0ULL;
#pragma unroll
            for (int e = 0; e < 16; e++) {
                float4 vn = *(const float4*)&sVnT[e * 128 + prow];
                ulonglong2 va = *(const ulonglong2*)&sVmT[e * 64 + c0];
                ulonglong2 vb = *(const ulonglong2*)&sVmT[e * 64 + c1];
                float vv[4] = {vn.x, vn.y, vn.z, vn.w};
#pragma unroll
                for (int i = 0; i < 4; i++) {
                    ULL ad = pack2(vv[i], vv[i]);
                    fma2(pa[i][0], ad, va.x); fma2(pa[i][1], ad, va.y);
                    fma2(pa[i][2], ad, vb.x); fma2(pa[i][3], ad, vb.y);
                }
            }
#pragma unroll
            for (int i = 0; i < 4; i++) {
                int row = prow + i;
                float2 p0 = unpack2(pa[i][0]);
                float2 p1 = unpack2(pa[i][1]);
                float2 p2 = unpack2(pa[i][2]);
                float2 p3 = unpack2(pa[i][3]);
                float4 o0 = make_float4(fmaxf(p0.x, 0.f), fmaxf(p0.y, 0.f),
                                        fmaxf(p1.x, 0.f), fmaxf(p1.y, 0.f));
                float4 o1 = make_float4(fmaxf(p2.x, 0.f), fmaxf(p2.y, 0.f),
                                        fmaxf(p3.x, 0.f), fmaxf(p3.y, 0.f));
                *(float4*)&sA[row * 64 + l0p] = o0;
                *(float4*)&sA[row * 64 + l1p] = o1;
            }
        }
        __syncthreads();

        // ---- Phase B: acc += A @ Xm (8 rows x 8 cols per thread) -----------
#pragma unroll 2
        for (int kf4 = 0; kf4 < 16; kf4++) {
            int laneA = ((kf4 ^ key0) << 2);
            int laneB = ((kf4 ^ key1) << 2);
            float4 a[8];
#pragma unroll
            for (int i = 0; i < 4; i++)
                a[i] = *(const float4*)&sA[(row0 + i) * 64 + laneA];
#pragma unroll
            for (int i = 4; i < 8; i++)
                a[i] = *(const float4*)&sA[(row0 + i) * 64 + laneB];
#pragma unroll
            for (int kk = 0; kk < 4; kk++) {
                int k = kf4 * 4 + kk;
                ulonglong2 xa = *(const ulonglong2*)&sXm[k * 64 + c0];
                ulonglong2 xb = *(const ulonglong2*)&sXm[k * 64 + c1];
#pragma unroll
                for (int i = 0; i < 8; i++) {
                    float av = (kk == 0) ? a[i].x : (kk == 1) ? a[i].y
                             : (kk == 2) ? a[i].z : a[i].w;
                    ULL ad = pack2(av, av);
                    fma2(acc[i][0], ad, xa.x);
                    fma2(acc[i][1], ad, xa.y);
                    fma2(acc[i][2], ad, xb.x);
                    fma2(acc[i][3], ad, xb.y);
                }
            }
        }
    }

    // epilogue: store partial (d_n already folded in)
    float* op = g_xg2p + (((size_t)ms * BB + b) * NN + n0) * 64;
#pragma unroll
    for (int i = 0; i < 8; i++) {
        int row = row0 + i;
        float2 q0 = unpack2(acc[i][0]);
        float2 q1 = unpack2(acc[i][1]);
        float2 q2 = unpack2(acc[i][2]);
        float2 q3 = unpack2(acc[i][3]);
        *(float4*)&op[(size_t)row * 64 + c0] = make_float4(q0.x, q0.y, q1.x, q1.y);
        *(float4*)&op[(size_t)row * 64 + c1] = make_float4(q2.x, q2.y, q3.x, q3.y);
    }
}

// ---------------- K5: out = x_g @ W[n] + bias (o-pair f32x2, R9/R13 proven) --
__global__ void k_out(const float* __restrict__ x, const float* __restrict__ emb1,
                      const float* __restrict__ bias_pool, float* __restrict__ out)
{
    __shared__ float sW[128 * 64];
    __shared__ float sxg[16][128];
    __shared__ float sbp[16 * 64];
    __shared__ float semb[16];
    int n = blockIdx.x;
    int tid = threadIdx.x;
    {
        const float4* wp = (const float4*)(g_W + (size_t)n * 8192);
        float4* sW4 = (float4*)sW;
#pragma unroll
        for (int i = 0; i < 8; i++) sW4[tid + i * 256] = wp[tid + i * 256];
    }
#pragma unroll
    for (int i = 0; i < 4; i++) sbp[tid + i * 256] = bias_pool[tid + i * 256];
    if (tid < 16) semb[tid] = emb1[(size_t)n * 16 + tid];
    {
        int bb = tid >> 4, lane = tid & 15;
        size_t rowoff = ((size_t)bb * NN + n) * 64;
        if (lane < 8) {
            const float4* xp = (const float4*)(x + rowoff);
            *(float4*)&sxg[bb][lane * 8]     = xp[lane * 2];
            *(float4*)&sxg[bb][lane * 8 + 4] = xp[lane * 2 + 1];
        } else {
            int l2 = lane - 8;
            float4 s0 = make_float4(0.f, 0.f, 0.f, 0.f);
            float4 s1 = make_float4(0.f, 0.f, 0.f, 0.f);
#pragma unroll
            for (int msx = 0; msx < 8; msx++) {
                const float4* gp = (const float4*)(g_xg2p + (size_t)msx * BB * NN * 64 + rowoff);
                float4 a = gp[l2 * 2], c = gp[l2 * 2 + 1];
                s0.x += a.x; s0.y += a.y; s0.z += a.z; s0.w += a.w;
                s1.x += c.x; s1.y += c.y; s1.z += c.z; s1.w += c.w;
            }
            *(float4*)&sxg[bb][64 + l2 * 8]     = s0;
            *(float4*)&sxg[bb][64 + l2 * 8 + 4] = s1;
        }
    }
    __syncthreads();

    int bb = tid >> 4, og = tid & 15;
    float4 accb = make_float4(0.f, 0.f, 0.f, 0.f);
#pragma unroll
    for (int e = 0; e < 16; e++) {
        float ev = semb[e];
        float4 bp4 = *(const float4*)&sbp[e * 64 + og * 4];
        accb.x = fmaf(ev, bp4.x, accb.x);
        accb.y = fmaf(ev, bp4.y, accb.y);
        accb.z = fmaf(ev, bp4.z, accb.z);
        accb.w = fmaf(ev, bp4.w, accb.w);
    }
    ULL acc0 = pack2(accb.x, accb.y);
    ULL acc1 = pack2(accb.z, accb.w);
#pragma unroll 4
    for (int kc = 0; kc < 128; kc++) {
        float xv = sxg[bb][kc];
        ULL xp = pack2(xv, xv);
        ulonglong2 w = *(const ulonglong2*)&sW[kc * 64 + og * 4];
        fma2(acc0, xp, w.x);
        fma2(acc1, xp, w.y);
    }
    float2 r0 = unpack2(acc0);
    float2 r1 = unpack2(acc1);
    size_t rowoff = ((size_t)bb * NN + n) * 64;
    *(float4*)&out[rowoff + og * 4] = make_float4(r0.x, r0.y, r1.x, r1.y);
}

// ---------------- launch (serial, proven order) -------------------------------
extern "C" void kernel_launch(void* const* d_in, const int* in_sizes, int n_in,
                              void* d_out, int out_size)
{
    const float* x    = (const float*)d_in[0];
    const float* emb0 = (const float*)d_in[1];
    const float* emb1 = (const float*)d_in[2];
    const float* w1   = (const float*)d_in[3];
    const float* b1   = (const float*)d_in[4];
    const float* w2   = (const float*)d_in[5];
    const float* b2   = (const float*)d_in[6];
    const float* w3   = (const float*)d_in[7];
    const float* b3   = (const float*)d_in[8];
    const float* wp   = (const float*)d_in[9];
    const float* bp   = (const float*)d_in[10];
    float* out = (float*)d_out;

    (void)in_sizes; (void)n_in; (void)out_size;

    const int smem_k_xg2 = (128 * 64 + 64 * 64 + 16 * 128 + 16 * 64) * 4;  // 61440 B
    cudaFuncSetAttribute(k_xg2, cudaFuncAttributeMaxDynamicSharedMemorySize, smem_k_xg2);

    k_nodevec<<<(BB * NN) / 256, 256>>>(x, emb0, w1, b1, w2, b2, w3, b3);
    k_wpre<<<dim3(8, 128), 256>>>(emb1, wp);
    k_dinv<<<dim3(8, 16, 8), 128>>>();
    k_dred<<<(BB * NN) / 256, 256>>>();
    k_xg2<<<dim3(16, 16, 8), 128, smem_k_xg2>>>(x);
    k_out<<<NN, 256>>>(x, emb1, bp, out);
}